// round 3
// baseline (speedup 1.0000x reference)
#include <cuda_runtime.h>
#include <cuda_bf16.h>
#include <math.h>

// Problem constants
#define BB 256   // batch
#define SS 512   // seq len
#define HH 1024  // hidden
#define EE 256   // input dim
#define CC 128   // num classes

// ---------------- device scratch (no allocations allowed) ----------------
__device__ float g_Gf[CC * HH];   // emb@Wfx^T + bf
__device__ float g_Gi[CC * HH];   // emb@Wix^T + bi
__device__ float g_Go[CC * HH];   // emb@Wox^T + bo
__device__ float g_Sc[CC * HH];   // sigmoid(emb@Wcx^T + bc)
__device__ float g_c0[BB * HH];   // ping-pong cell state
__device__ float g_c1[BB * HH];
__device__ float g_h [BB * HH];   // final hidden

// ---------------- helpers ----------------
__device__ __forceinline__ float sigmoidf_(float x) {
    return 1.0f / (1.0f + expf(-x));
}

__device__ __forceinline__ unsigned long long pk2(float lo, float hi) {
    unsigned long long r;
    asm("mov.b64 %0, {%1, %2};" : "=l"(r) : "f"(lo), "f"(hi));
    return r;
}
__device__ __forceinline__ unsigned long long pk2b(float v) {
    unsigned long long r;
    asm("mov.b64 %0, {%1, %1};" : "=l"(r) : "f"(v));
    return r;
}
__device__ __forceinline__ void upk2(unsigned long long v, float& lo, float& hi) {
    asm("mov.b64 {%0, %1}, %2;" : "=f"(lo), "=f"(hi) : "l"(v));
}
// packed dual fp32 FMA (Blackwell f32x2 path; ptxas never emits this from C++)
__device__ __forceinline__ unsigned long long fma2(unsigned long long a,
                                                   unsigned long long b,
                                                   unsigned long long c) {
    unsigned long long d;
    asm("fma.rn.f32x2 %0, %1, %2, %3;" : "=l"(d) : "l"(a), "l"(b), "l"(c));
    return d;
}

// ---------------- kernel 0: zero the initial cell state ----------------
__global__ void zero_kernel() {
    int i = blockIdx.x * blockDim.x + threadIdx.x;  // 256*256 = 65536 float4
    reinterpret_cast<float4*>(g_c0)[i] = make_float4(0.f, 0.f, 0.f, 0.f);
}

// ---------------- kernel 1: precompute class->gate tables ----------------
// out[cls][h] for 4 tables. M=128 (cls), N=1024 (h), K=256.
// grid: (32 h-tiles, 4 cls-tiles), 256 threads.
__global__ __launch_bounds__(256)
void tab_kernel(const float* __restrict__ emb,
                const float* __restrict__ Wfx, const float* __restrict__ Wix,
                const float* __restrict__ Wox, const float* __restrict__ Wcx,
                const float* __restrict__ bf,  const float* __restrict__ bi,
                const float* __restrict__ bo,  const float* __restrict__ bc) {
    __shared__ float es[32][33];      // [cls][k]
    __shared__ float ws[4][32][33];   // [table][h][k]

    const int tid = threadIdx.x;
    const int h0  = blockIdx.x * 32;
    const int c0b = blockIdx.y * 32;
    const int tx  = tid & 31;         // h within tile
    const int ty  = tid >> 5;         // 0..7 (cls sub-row)

    float acc[4][4];
#pragma unroll
    for (int m = 0; m < 4; m++)
#pragma unroll
        for (int q = 0; q < 4; q++) acc[m][q] = 0.f;

    for (int k0 = 0; k0 < EE; k0 += 32) {
        __syncthreads();
        const int ccol  = tid & 31;
        const int rbase = tid >> 5;
#pragma unroll
        for (int rr = 0; rr < 4; rr++) {
            const int r = rbase + rr * 8;
            es[r][ccol]    = emb[(c0b + r) * EE + k0 + ccol];
            ws[0][r][ccol] = Wfx[(h0 + r) * EE + k0 + ccol];
            ws[1][r][ccol] = Wix[(h0 + r) * EE + k0 + ccol];
            ws[2][r][ccol] = Wox[(h0 + r) * EE + k0 + ccol];
            ws[3][r][ccol] = Wcx[(h0 + r) * EE + k0 + ccol];
        }
        __syncthreads();
#pragma unroll
        for (int kk = 0; kk < 32; kk++) {
            const float b0 = ws[0][tx][kk];
            const float b1 = ws[1][tx][kk];
            const float b2 = ws[2][tx][kk];
            const float b3 = ws[3][tx][kk];
#pragma unroll
            for (int q = 0; q < 4; q++) {
                const float a = es[ty + q * 8][kk];
                acc[0][q] = fmaf(a, b0, acc[0][q]);
                acc[1][q] = fmaf(a, b1, acc[1][q]);
                acc[2][q] = fmaf(a, b2, acc[2][q]);
                acc[3][q] = fmaf(a, b3, acc[3][q]);
            }
        }
    }

    const int h   = h0 + tx;
    const float vbf = bf[h], vbi = bi[h], vbo = bo[h], vbc = bc[h];
#pragma unroll
    for (int q = 0; q < 4; q++) {
        const int cls = c0b + ty + q * 8;
        g_Gf[cls * HH + h] = acc[0][q] + vbf;
        g_Gi[cls * HH + h] = acc[1][q] + vbi;
        g_Go[cls * HH + h] = acc[2][q] + vbo;
        g_Sc[cls * HH + h] = sigmoidf_(acc[3][q] + vbc);
    }
}

// ---------------- kernel 2: one recurrence step ----------------
// c_out[b,n] = Sc[cls,n]*sig(Gi[cls,n]+c.Wih[n]) + c[b,n]*sig(Gf[cls,n]+c.Wfh[n])
// GEMM M=256(b) x N=1024(n) x K=1024, two B matrices sharing the A tile.
// grid: (32 n-tiles of 32, 4 m-tiles of 64), 256 threads.
__global__ __launch_bounds__(256)
void step_kernel(const int* __restrict__ x, int t,
                 const float* __restrict__ Wfh, const float* __restrict__ Wih) {
    const float* __restrict__ cin  = (t & 1) ? g_c1 : g_c0;
    float*       __restrict__ cout = (t & 1) ? g_c0 : g_c1;

    __shared__ __align__(16) float a_s[32][64];   // [k][m]
    __shared__ __align__(16) float wf_s[32][32];  // [k][n]
    __shared__ __align__(16) float wi_s[32][32];
    __shared__ int cls_s[64];

    const int tid = threadIdx.x;
    const int M0  = blockIdx.y * 64;
    const int N0  = blockIdx.x * 32;
    if (tid < 64) cls_s[tid] = x[(M0 + tid) * SS + t];

    const int tx = tid & 31;   // n within tile
    const int ty = tid >> 5;   // 0..7 -> m rows [ty*8, ty*8+8)

    unsigned long long accf[4], acci[4];
#pragma unroll
    for (int p = 0; p < 4; p++) { accf[p] = 0ull; acci[p] = 0ull; }

    const int k4  = (tid & 7) * 4;
    const int row = tid >> 3;  // 0..31

    for (int k0 = 0; k0 < HH; k0 += 32) {
        __syncthreads();
        // A tile: 64 rows of c, transposed into [k][m]
        {
            const float4 v0 = *reinterpret_cast<const float4*>(&cin[(M0 + row)      * HH + k0 + k4]);
            const float4 v1 = *reinterpret_cast<const float4*>(&cin[(M0 + row + 32) * HH + k0 + k4]);
            a_s[k4 + 0][row] = v0.x; a_s[k4 + 1][row] = v0.y;
            a_s[k4 + 2][row] = v0.z; a_s[k4 + 3][row] = v0.w;
            a_s[k4 + 0][row + 32] = v1.x; a_s[k4 + 1][row + 32] = v1.y;
            a_s[k4 + 2][row + 32] = v1.z; a_s[k4 + 3][row + 32] = v1.w;
            const float4 f4 = *reinterpret_cast<const float4*>(&Wfh[(N0 + row) * HH + k0 + k4]);
            wf_s[k4 + 0][row] = f4.x; wf_s[k4 + 1][row] = f4.y;
            wf_s[k4 + 2][row] = f4.z; wf_s[k4 + 3][row] = f4.w;
            const float4 i4 = *reinterpret_cast<const float4*>(&Wih[(N0 + row) * HH + k0 + k4]);
            wi_s[k4 + 0][row] = i4.x; wi_s[k4 + 1][row] = i4.y;
            wi_s[k4 + 2][row] = i4.z; wi_s[k4 + 3][row] = i4.w;
        }
        __syncthreads();
#pragma unroll
        for (int kk = 0; kk < 32; kk++) {
            const unsigned long long wf2 = pk2b(wf_s[kk][tx]);
            const unsigned long long wi2 = pk2b(wi_s[kk][tx]);
            const float4 a0 = *reinterpret_cast<const float4*>(&a_s[kk][ty * 8]);
            const float4 a1 = *reinterpret_cast<const float4*>(&a_s[kk][ty * 8 + 4]);
            const unsigned long long ap0 = pk2(a0.x, a0.y);
            const unsigned long long ap1 = pk2(a0.z, a0.w);
            const unsigned long long ap2 = pk2(a1.x, a1.y);
            const unsigned long long ap3 = pk2(a1.z, a1.w);
            accf[0] = fma2(ap0, wf2, accf[0]);  acci[0] = fma2(ap0, wi2, acci[0]);
            accf[1] = fma2(ap1, wf2, accf[1]);  acci[1] = fma2(ap1, wi2, acci[1]);
            accf[2] = fma2(ap2, wf2, accf[2]);  acci[2] = fma2(ap2, wi2, acci[2]);
            accf[3] = fma2(ap3, wf2, accf[3]);  acci[3] = fma2(ap3, wi2, acci[3]);
        }
    }

    const int n = N0 + tx;
#pragma unroll
    for (int p = 0; p < 4; p++) {
        float flo, fhi, ilo, ihi;
        upk2(accf[p], flo, fhi);
        upk2(acci[p], ilo, ihi);
        const int m0 = ty * 8 + p * 2;
#pragma unroll
        for (int j = 0; j < 2; j++) {
            const int   m   = m0 + j;
            const int   b   = M0 + m;
            const int   cls = cls_s[m];
            const float av  = (j == 0) ? flo : fhi;
            const float bv  = (j == 0) ? ilo : ihi;
            const float f   = sigmoidf_(av + g_Gf[cls * HH + n]);
            const float ii  = sigmoidf_(bv + g_Gi[cls * HH + n]);
            const float co  = cin[b * HH + n];
            cout[b * HH + n] = g_Sc[cls * HH + n] * ii + co * f;
        }
    }
}

// ---------------- kernel 3: final o-gate + hidden ----------------
// After 512 steps: c_last = g_c0, c_prev = g_c1.
// h[b,n] = tanh(c_last[b,n]) * sig(Go[cls,n] + c_prev[b].Woh[n])
__global__ __launch_bounds__(256)
void final_o_kernel(const int* __restrict__ x, const float* __restrict__ Woh) {
    const float* __restrict__ cprev = g_c1;
    const float* __restrict__ clast = g_c0;

    __shared__ __align__(16) float a_s[32][64];
    __shared__ __align__(16) float wo_s[32][32];
    __shared__ int cls_s[64];

    const int tid = threadIdx.x;
    const int M0  = blockIdx.y * 64;
    const int N0  = blockIdx.x * 32;
    if (tid < 64) cls_s[tid] = x[(M0 + tid) * SS + (SS - 1)];

    const int tx = tid & 31;
    const int ty = tid >> 5;

    unsigned long long acco[4];
#pragma unroll
    for (int p = 0; p < 4; p++) acco[p] = 0ull;

    const int k4  = (tid & 7) * 4;
    const int row = tid >> 3;

    for (int k0 = 0; k0 < HH; k0 += 32) {
        __syncthreads();
        {
            const float4 v0 = *reinterpret_cast<const float4*>(&cprev[(M0 + row)      * HH + k0 + k4]);
            const float4 v1 = *reinterpret_cast<const float4*>(&cprev[(M0 + row + 32) * HH + k0 + k4]);
            a_s[k4 + 0][row] = v0.x; a_s[k4 + 1][row] = v0.y;
            a_s[k4 + 2][row] = v0.z; a_s[k4 + 3][row] = v0.w;
            a_s[k4 + 0][row + 32] = v1.x; a_s[k4 + 1][row + 32] = v1.y;
            a_s[k4 + 2][row + 32] = v1.z; a_s[k4 + 3][row + 32] = v1.w;
            const float4 o4 = *reinterpret_cast<const float4*>(&Woh[(N0 + row) * HH + k0 + k4]);
            wo_s[k4 + 0][row] = o4.x; wo_s[k4 + 1][row] = o4.y;
            wo_s[k4 + 2][row] = o4.z; wo_s[k4 + 3][row] = o4.w;
        }
        __syncthreads();
#pragma unroll
        for (int kk = 0; kk < 32; kk++) {
            const unsigned long long wo2 = pk2b(wo_s[kk][tx]);
            const float4 a0 = *reinterpret_cast<const float4*>(&a_s[kk][ty * 8]);
            const float4 a1 = *reinterpret_cast<const float4*>(&a_s[kk][ty * 8 + 4]);
            acco[0] = fma2(pk2(a0.x, a0.y), wo2, acco[0]);
            acco[1] = fma2(pk2(a0.z, a0.w), wo2, acco[1]);
            acco[2] = fma2(pk2(a1.x, a1.y), wo2, acco[2]);
            acco[3] = fma2(pk2(a1.z, a1.w), wo2, acco[3]);
        }
    }

    const int n = N0 + tx;
#pragma unroll
    for (int p = 0; p < 4; p++) {
        float olo, ohi;
        upk2(acco[p], olo, ohi);
        const int m0 = ty * 8 + p * 2;
#pragma unroll
        for (int j = 0; j < 2; j++) {
            const int   m   = m0 + j;
            const int   b   = M0 + m;
            const int   cls = cls_s[m];
            const float av  = (j == 0) ? olo : ohi;
            const float o   = sigmoidf_(av + g_Go[cls * HH + n]);
            g_h[b * HH + n] = tanhf(clast[b * HH + n]) * o;
        }
    }
}

// ---------------- kernel 4: logits + log_softmax ----------------
// p[b,j] = h[b].Wph[j] + bp[j];  out = p - logsumexp(p)
__global__ __launch_bounds__(128)
void logits_kernel(const float* __restrict__ Wph, const float* __restrict__ bp,
                   float* __restrict__ out) {
    const int b = blockIdx.x;
    const int j = threadIdx.x;

    __shared__ __align__(16) float h_s[HH];
    __shared__ float red[128];

    const float4* hv  = reinterpret_cast<const float4*>(&g_h[b * HH]);
    float4*       hs4 = reinterpret_cast<float4*>(h_s);
    for (int i = j; i < HH / 4; i += 128) hs4[i] = hv[i];
    __syncthreads();

    float acc = 0.f;
    const float4* w4 = reinterpret_cast<const float4*>(&Wph[j * HH]);
#pragma unroll 4
    for (int k = 0; k < HH / 4; k++) {
        const float4 w = w4[k];
        const float4 h = hs4[k];
        acc = fmaf(h.x, w.x, acc);
        acc = fmaf(h.y, w.y, acc);
        acc = fmaf(h.z, w.z, acc);
        acc = fmaf(h.w, w.w, acc);
    }
    const float p = acc + bp[j];

    red[j] = p;
    __syncthreads();
    for (int s2 = 64; s2 > 0; s2 >>= 1) {
        if (j < s2) red[j] = fmaxf(red[j], red[j + s2]);
        __syncthreads();
    }
    const float mx = red[0];
    __syncthreads();
    red[j] = expf(p - mx);
    __syncthreads();
    for (int s2 = 64; s2 > 0; s2 >>= 1) {
        if (j < s2) red[j] += red[j + s2];
        __syncthreads();
    }
    const float lse = logf(red[0]) + mx;
    out[b * CC + j] = p - lse;
}

// ---------------- launcher ----------------
extern "C" void kernel_launch(void* const* d_in, const int* in_sizes, int n_in,
                              void* d_out, int out_size) {
    const int*   x   = (const int*)  d_in[0];
    const float* emb = (const float*)d_in[1];
    const float* Wcx = (const float*)d_in[2];
    const float* bc  = (const float*)d_in[3];
    const float* Wix = (const float*)d_in[4];
    const float* Wih = (const float*)d_in[5];
    const float* bi  = (const float*)d_in[6];
    const float* Wfx = (const float*)d_in[7];
    const float* Wfh = (const float*)d_in[8];
    const float* bf  = (const float*)d_in[9];
    const float* Wox = (const float*)d_in[10];
    const float* Woh = (const float*)d_in[11];
    const float* bo  = (const float*)d_in[12];
    const float* Wph = (const float*)d_in[13];
    const float* bp  = (const float*)d_in[14];
    float* out = (float*)d_out;

    tab_kernel<<<dim3(32, 4), 256>>>(emb, Wfx, Wix, Wox, Wcx, bf, bi, bo, bc);
    zero_kernel<<<256, 256>>>();

    for (int t = 0; t < SS; t++) {
        step_kernel<<<dim3(32, 4), 256>>>(x, t, Wfh, Wih);
    }

    final_o_kernel<<<dim3(32, 4), 256>>>(x, Woh);
    logits_kernel<<<BB, 128>>>(Wph, bp, out);
}

// round 4
// speedup vs baseline: 1.6704x; 1.6704x over previous
#include <cuda_runtime.h>
#include <cuda_bf16.h>
#include <math.h>

// Problem constants
#define BB 256   // batch
#define SS 512   // seq len
#define HH 1024  // hidden
#define EE 256   // input dim
#define CC 128   // num classes

typedef unsigned long long u64;

// ---------------- device scratch (no allocations allowed) ----------------
__device__ float g_Gf[CC * HH];        // emb@Wfx^T + bf
__device__ float g_Gi[CC * HH];        // emb@Wix^T + bi
__device__ float g_Go[CC * HH];        // emb@Wox^T + bo
__device__ float g_Sc[CC * HH];        // sigmoid(emb@Wcx^T + bc)
__device__ u64   g_c2[2][HH * (BB/2)]; // cell state, transposed+paired: [buf][k*128 + bpair]
__device__ float g_WfT[HH * HH];       // Wfh transposed -> [k][n]
__device__ float g_WiT[HH * HH];
__device__ float g_WoT[HH * HH];
__device__ float g_h [BB * HH];        // final hidden (row-major [b][h])

// ---------------- helpers ----------------
__device__ __forceinline__ float sigmoidf_(float x) {
    return 1.0f / (1.0f + __expf(-x));
}
__device__ __forceinline__ u64 pk2(float lo, float hi) {
    u64 r; asm("mov.b64 %0, {%1, %2};" : "=l"(r) : "f"(lo), "f"(hi)); return r;
}
__device__ __forceinline__ u64 pk2b(float v) {
    u64 r; asm("mov.b64 %0, {%1, %1};" : "=l"(r) : "f"(v)); return r;
}
__device__ __forceinline__ void upk2(u64 v, float& lo, float& hi) {
    asm("mov.b64 {%0, %1}, %2;" : "=f"(lo), "=f"(hi) : "l"(v));
}
__device__ __forceinline__ u64 fma2(u64 a, u64 b, u64 c) {
    u64 d; asm("fma.rn.f32x2 %0, %1, %2, %3;" : "=l"(d) : "l"(a), "l"(b), "l"(c)); return d;
}
__device__ __forceinline__ unsigned int smem_u32(const void* p) {
    return (unsigned int)__cvta_generic_to_shared(p);
}
__device__ __forceinline__ void cpa16(void* dst, const void* src) {
    asm volatile("cp.async.cg.shared.global [%0], [%1], 16;\n"
                 :: "r"(smem_u32(dst)), "l"(src));
}
#define CP_COMMIT() asm volatile("cp.async.commit_group;\n" ::: "memory")
#define CP_WAIT0()  asm volatile("cp.async.wait_group 0;\n" ::: "memory")

// ---------------- kernel: zero the initial (transposed) cell state ----------------
__global__ void zero_kernel() {
    int i = blockIdx.x * blockDim.x + threadIdx.x;  // 256*256 = 65536 float4 = 1MB
    reinterpret_cast<float4*>(g_c2[0])[i] = make_float4(0.f, 0.f, 0.f, 0.f);
}

// ---------------- kernel: 32x32 tiled transpose [n][k] -> [k][n] ----------------
__global__ __launch_bounds__(256)
void transpose_kernel(const float* __restrict__ in, float* __restrict__ out) {
    __shared__ float t[32][33];
    const int k0 = blockIdx.x * 32;
    const int n0 = blockIdx.y * 32;
    const int tx = threadIdx.x & 31;
    const int ty = threadIdx.x >> 5;   // 0..7
#pragma unroll
    for (int r = 0; r < 4; r++) {
        const int row = ty + r * 8;
        t[row][tx] = in[(size_t)(n0 + row) * HH + k0 + tx];
    }
    __syncthreads();
#pragma unroll
    for (int r = 0; r < 4; r++) {
        const int row = ty + r * 8;
        out[(size_t)(k0 + row) * HH + n0 + tx] = t[tx][row];
    }
}

// ---------------- kernel: precompute class->gate tables ----------------
// M=128 (cls), N=1024 (h), K=256.  grid: (32 h-tiles, 4 cls-tiles), 256 threads.
__global__ __launch_bounds__(256)
void tab_kernel(const float* __restrict__ emb,
                const float* __restrict__ Wfx, const float* __restrict__ Wix,
                const float* __restrict__ Wox, const float* __restrict__ Wcx,
                const float* __restrict__ bf,  const float* __restrict__ bi,
                const float* __restrict__ bo,  const float* __restrict__ bc) {
    __shared__ float es[32][33];      // [cls][k]
    __shared__ float ws[4][32][33];   // [table][h][k]

    const int tid = threadIdx.x;
    const int h0  = blockIdx.x * 32;
    const int c0b = blockIdx.y * 32;
    const int tx  = tid & 31;
    const int ty  = tid >> 5;

    float acc[4][4];
#pragma unroll
    for (int m = 0; m < 4; m++)
#pragma unroll
        for (int q = 0; q < 4; q++) acc[m][q] = 0.f;

    for (int k0 = 0; k0 < EE; k0 += 32) {
        __syncthreads();
        const int ccol  = tid & 31;
        const int rbase = tid >> 5;
#pragma unroll
        for (int rr = 0; rr < 4; rr++) {
            const int r = rbase + rr * 8;
            es[r][ccol]    = emb[(c0b + r) * EE + k0 + ccol];
            ws[0][r][ccol] = Wfx[(h0 + r) * EE + k0 + ccol];
            ws[1][r][ccol] = Wix[(h0 + r) * EE + k0 + ccol];
            ws[2][r][ccol] = Wox[(h0 + r) * EE + k0 + ccol];
            ws[3][r][ccol] = Wcx[(h0 + r) * EE + k0 + ccol];
        }
        __syncthreads();
#pragma unroll
        for (int kk = 0; kk < 32; kk++) {
            const float b0 = ws[0][tx][kk];
            const float b1 = ws[1][tx][kk];
            const float b2 = ws[2][tx][kk];
            const float b3 = ws[3][tx][kk];
#pragma unroll
            for (int q = 0; q < 4; q++) {
                const float a = es[ty + q * 8][kk];
                acc[0][q] = fmaf(a, b0, acc[0][q]);
                acc[1][q] = fmaf(a, b1, acc[1][q]);
                acc[2][q] = fmaf(a, b2, acc[2][q]);
                acc[3][q] = fmaf(a, b3, acc[3][q]);
            }
        }
    }

    const int h = h0 + tx;
    const float vbf = bf[h], vbi = bi[h], vbo = bo[h], vbc = bc[h];
#pragma unroll
    for (int q = 0; q < 4; q++) {
        const int cls = c0b + ty + q * 8;
        g_Gf[cls * HH + h] = acc[0][q] + vbf;
        g_Gi[cls * HH + h] = acc[1][q] + vbi;
        g_Go[cls * HH + h] = acc[2][q] + vbo;
        g_Sc[cls * HH + h] = sigmoidf_(acc[3][q] + vbc);
    }
}

// ---------------- kernel: one recurrence step (double-buffered cp.async) ----------------
// c_out[b,n] = Sc[cls,n]*sig(Gi[cls,n]+c.Wih[n]) + c[b,n]*sig(Gf[cls,n]+c.Wfh[n])
// GEMM M=256(b) x N=1024(n) x K=1024. A (cell state) is stored transposed and
// b-paired as u64 so FFMA2 operands load pre-packed. W stored transposed [k][n].
// Tile: M=64, N=32. grid (32 n-tiles, 4 m-tiles), 256 threads (8 warps).
__global__ __launch_bounds__(256)
void step_kernel(const int* __restrict__ x, int t) {
    const u64* __restrict__ cin  = g_c2[t & 1];
    u64*       __restrict__ cout = g_c2[(t & 1) ^ 1];

    __shared__ __align__(16) u64   a_s [2][32][32];  // [buf][kk][bpair]  16KB
    __shared__ __align__(16) float wf_s[2][32][32];  // [buf][kk][n]       8KB
    __shared__ __align__(16) float wi_s[2][32][32];  //                    8KB
    __shared__ int cls_s[64];

    const int tid = threadIdx.x;
    const int M0  = blockIdx.y * 64;   // batch offset
    const int N0  = blockIdx.x * 32;   // hidden offset
    if (tid < 64) cls_s[tid] = x[(M0 + tid) * SS + t];

    const int tx  = tid & 31;          // n lane
    const int ty  = tid >> 5;          // m-group (8 groups x 4 bpairs)
    const int mpb = ty * 4;            // block-local bpair base

    // cp.async source/dest assignment: 32 rows; A row = 32 u64 (2x16B per thread),
    // W row = 32 floats (1x16B per thread)
    const int prow = tid >> 3;         // 0..31
    const int pcol = tid & 7;          // 0..7
    const u64*   aS = cin   + (size_t)prow * (BB/2) + (M0 >> 1) + pcol * 4;
    const float* fS = g_WfT + (size_t)prow * HH + N0 + pcol * 4;
    const float* iS = g_WiT + (size_t)prow * HH + N0 + pcol * 4;

    u64 accf[4], acci[4];
#pragma unroll
    for (int p = 0; p < 4; p++) { accf[p] = 0ull; acci[p] = 0ull; }

    // prefetch tile 0 into buf 0
    {
        cpa16(&a_s [0][prow][pcol * 4],     aS);
        cpa16(&a_s [0][prow][pcol * 4 + 2], aS + 2);
        cpa16(&wf_s[0][prow][pcol * 4],     fS);
        cpa16(&wi_s[0][prow][pcol * 4],     iS);
        CP_COMMIT();
    }

    for (int it = 0; it < 32; it++) {
        const int buf = it & 1;
        CP_WAIT0();
        __syncthreads();          // tile `it` resident; all warps past tile it-1

        if (it < 31) {            // prefetch tile it+1 into the other buffer
            const size_t aoff = (size_t)(it + 1) * 32 * (BB/2);
            const size_t woff = (size_t)(it + 1) * 32 * HH;
            cpa16(&a_s [buf ^ 1][prow][pcol * 4],     aS + aoff);
            cpa16(&a_s [buf ^ 1][prow][pcol * 4 + 2], aS + aoff + 2);
            cpa16(&wf_s[buf ^ 1][prow][pcol * 4],     fS + woff);
            cpa16(&wi_s[buf ^ 1][prow][pcol * 4],     iS + woff);
            CP_COMMIT();
        }

#pragma unroll
        for (int kk = 0; kk < 32; kk++) {
            const u64 wf2 = pk2b(wf_s[buf][kk][tx]);
            const u64 wi2 = pk2b(wi_s[buf][kk][tx]);
            const ulonglong2 A01 = *reinterpret_cast<const ulonglong2*>(&a_s[buf][kk][mpb]);
            const ulonglong2 A23 = *reinterpret_cast<const ulonglong2*>(&a_s[buf][kk][mpb + 2]);
            accf[0] = fma2(A01.x, wf2, accf[0]);  acci[0] = fma2(A01.x, wi2, acci[0]);
            accf[1] = fma2(A01.y, wf2, accf[1]);  acci[1] = fma2(A01.y, wi2, acci[1]);
            accf[2] = fma2(A23.x, wf2, accf[2]);  acci[2] = fma2(A23.x, wi2, acci[2]);
            accf[3] = fma2(A23.y, wf2, accf[3]);  acci[3] = fma2(A23.y, wi2, acci[3]);
        }
    }

    // epilogue: gates + cell update; c2T element for (b,n) shares our lane's n
    const int n = N0 + tx;
#pragma unroll
    for (int p = 0; p < 4; p++) {
        const int mp = (M0 >> 1) + mpb + p;       // global bpair
        float flo, fhi, ilo, ihi;
        upk2(accf[p], flo, fhi);
        upk2(acci[p], ilo, ihi);
        float c0o, c1o;
        upk2(cin[(size_t)n * (BB/2) + mp], c0o, c1o);
        const int lm   = 2 * (mpb + p);           // block-local batch index
        const int cls0 = cls_s[lm];
        const int cls1 = cls_s[lm + 1];
        const float f0 = sigmoidf_(flo + g_Gf[cls0 * HH + n]);
        const float i0 = sigmoidf_(ilo + g_Gi[cls0 * HH + n]);
        const float f1 = sigmoidf_(fhi + g_Gf[cls1 * HH + n]);
        const float i1 = sigmoidf_(ihi + g_Gi[cls1 * HH + n]);
        const float cn0 = g_Sc[cls0 * HH + n] * i0 + c0o * f0;
        const float cn1 = g_Sc[cls1 * HH + n] * i1 + c1o * f1;
        cout[(size_t)n * (BB/2) + mp] = pk2(cn0, cn1);
    }
}

// ---------------- kernel: final o-gate + hidden ----------------
// clast = g_c2[0] (written by t=511), cprev = g_c2[1] (written by t=510).
// h[b,n] = tanh(clast[b,n]) * sig(Go[cls,n] + cprev[b].Woh[n])
__global__ __launch_bounds__(256)
void final_o_kernel(const int* __restrict__ x) {
    const u64* __restrict__ cprev = g_c2[1];
    const u64* __restrict__ clast = g_c2[0];

    __shared__ __align__(16) u64   a_s [2][32][32];
    __shared__ __align__(16) float wo_s[2][32][32];
    __shared__ int cls_s[64];

    const int tid = threadIdx.x;
    const int M0  = blockIdx.y * 64;
    const int N0  = blockIdx.x * 32;
    if (tid < 64) cls_s[tid] = x[(M0 + tid) * SS + (SS - 1)];

    const int tx  = tid & 31;
    const int ty  = tid >> 5;
    const int mpb = ty * 4;

    const int prow = tid >> 3;
    const int pcol = tid & 7;
    const u64*   aS = cprev + (size_t)prow * (BB/2) + (M0 >> 1) + pcol * 4;
    const float* oS = g_WoT + (size_t)prow * HH + N0 + pcol * 4;

    u64 acco[4];
#pragma unroll
    for (int p = 0; p < 4; p++) acco[p] = 0ull;

    {
        cpa16(&a_s [0][prow][pcol * 4],     aS);
        cpa16(&a_s [0][prow][pcol * 4 + 2], aS + 2);
        cpa16(&wo_s[0][prow][pcol * 4],     oS);
        CP_COMMIT();
    }

    for (int it = 0; it < 32; it++) {
        const int buf = it & 1;
        CP_WAIT0();
        __syncthreads();
        if (it < 31) {
            const size_t aoff = (size_t)(it + 1) * 32 * (BB/2);
            const size_t woff = (size_t)(it + 1) * 32 * HH;
            cpa16(&a_s [buf ^ 1][prow][pcol * 4],     aS + aoff);
            cpa16(&a_s [buf ^ 1][prow][pcol * 4 + 2], aS + aoff + 2);
            cpa16(&wo_s[buf ^ 1][prow][pcol * 4],     oS + woff);
            CP_COMMIT();
        }
#pragma unroll
        for (int kk = 0; kk < 32; kk++) {
            const u64 wo2 = pk2b(wo_s[buf][kk][tx]);
            const ulonglong2 A01 = *reinterpret_cast<const ulonglong2*>(&a_s[buf][kk][mpb]);
            const ulonglong2 A23 = *reinterpret_cast<const ulonglong2*>(&a_s[buf][kk][mpb + 2]);
            acco[0] = fma2(A01.x, wo2, acco[0]);
            acco[1] = fma2(A01.y, wo2, acco[1]);
            acco[2] = fma2(A23.x, wo2, acco[2]);
            acco[3] = fma2(A23.y, wo2, acco[3]);
        }
    }

    const int n = N0 + tx;
#pragma unroll
    for (int p = 0; p < 4; p++) {
        const int mp = (M0 >> 1) + mpb + p;
        float olo, ohi;
        upk2(acco[p], olo, ohi);
        float cl0, cl1;
        upk2(clast[(size_t)n * (BB/2) + mp], cl0, cl1);
        const int lm   = 2 * (mpb + p);
        const int cls0 = cls_s[lm];
        const int cls1 = cls_s[lm + 1];
        const float o0 = sigmoidf_(olo + g_Go[cls0 * HH + n]);
        const float o1 = sigmoidf_(ohi + g_Go[cls1 * HH + n]);
        g_h[(size_t)(2 * mp)     * HH + n] = tanhf(cl0) * o0;
        g_h[(size_t)(2 * mp + 1) * HH + n] = tanhf(cl1) * o1;
    }
}

// ---------------- kernel: logits + log_softmax ----------------
__global__ __launch_bounds__(128)
void logits_kernel(const float* __restrict__ Wph, const float* __restrict__ bp,
                   float* __restrict__ out) {
    const int b = blockIdx.x;
    const int j = threadIdx.x;

    __shared__ __align__(16) float h_s[HH];
    __shared__ float red[128];

    const float4* hv  = reinterpret_cast<const float4*>(&g_h[(size_t)b * HH]);
    float4*       hs4 = reinterpret_cast<float4*>(h_s);
    for (int i = j; i < HH / 4; i += 128) hs4[i] = hv[i];
    __syncthreads();

    float acc = 0.f;
    const float4* w4 = reinterpret_cast<const float4*>(&Wph[(size_t)j * HH]);
#pragma unroll 4
    for (int k = 0; k < HH / 4; k++) {
        const float4 w = w4[k];
        const float4 h = hs4[k];
        acc = fmaf(h.x, w.x, acc);
        acc = fmaf(h.y, w.y, acc);
        acc = fmaf(h.z, w.z, acc);
        acc = fmaf(h.w, w.w, acc);
    }
    const float p = acc + bp[j];

    red[j] = p;
    __syncthreads();
    for (int s2 = 64; s2 > 0; s2 >>= 1) {
        if (j < s2) red[j] = fmaxf(red[j], red[j + s2]);
        __syncthreads();
    }
    const float mx = red[0];
    __syncthreads();
    red[j] = expf(p - mx);
    __syncthreads();
    for (int s2 = 64; s2 > 0; s2 >>= 1) {
        if (j < s2) red[j] += red[j + s2];
        __syncthreads();
    }
    const float lse = logf(red[0]) + mx;
    out[b * CC + j] = p - lse;
}

// ---------------- launcher ----------------
extern "C" void kernel_launch(void* const* d_in, const int* in_sizes, int n_in,
                              void* d_out, int out_size) {
    const int*   x   = (const int*)  d_in[0];
    const float* emb = (const float*)d_in[1];
    const float* Wcx = (const float*)d_in[2];
    const float* bc  = (const float*)d_in[3];
    const float* Wix = (const float*)d_in[4];
    const float* Wih = (const float*)d_in[5];
    const float* bi  = (const float*)d_in[6];
    const float* Wfx = (const float*)d_in[7];
    const float* Wfh = (const float*)d_in[8];
    const float* bf  = (const float*)d_in[9];
    const float* Wox = (const float*)d_in[10];
    const float* Woh = (const float*)d_in[11];
    const float* bo  = (const float*)d_in[12];
    const float* Wph = (const float*)d_in[13];
    const float* bp  = (const float*)d_in[14];
    float* out = (float*)d_out;

    float* wfT; cudaGetSymbolAddress((void**)&wfT, g_WfT);
    float* wiT; cudaGetSymbolAddress((void**)&wiT, g_WiT);
    float* woT; cudaGetSymbolAddress((void**)&woT, g_WoT);

    transpose_kernel<<<dim3(32, 32), 256>>>(Wfh, wfT);
    transpose_kernel<<<dim3(32, 32), 256>>>(Wih, wiT);
    transpose_kernel<<<dim3(32, 32), 256>>>(Woh, woT);
    tab_kernel<<<dim3(32, 4), 256>>>(emb, Wfx, Wix, Wox, Wcx, bf, bi, bo, bc);
    zero_kernel<<<256, 256>>>();

    for (int t = 0; t < SS; t++) {
        step_kernel<<<dim3(32, 4), 256>>>(x, t);
    }

    final_o_kernel<<<dim3(32, 4), 256>>>(x);
    logits_kernel<<<BB, 128>>>(Wph, bp, out);
}